// round 17
// baseline (speedup 1.0000x reference)
#include <cuda_runtime.h>
#include <cuda_fp16.h>
#include <cstdint>

// ============================================================================
// Problem constants
// ============================================================================
#define B_DIM   256
#define T_DIM   2048
#define K_DIM   64
#define H_DIM   128
#define TILE_T  32
#define N_TILES (T_DIM / TILE_T)   // 64

// Scan: y_t = 0.9*y_{t-1} - 1.25*th_{t-1} + g_t, th = tanh(y), spk = .5th+.5
// g = 2.5*ff - 1.5  (2.5 folded into W, bias' = 2.5b - 1.5)
// GEMM: 2-term fp16 split  ff ~= wh*xh + wh*xl,  xl = fp16(x - xh)

// ============================================================================
// SMEM layout (bytes) — 101376 total (2 CTAs/SM)
//   [0, 27648)        x ring: 3 slots x 9216 (fp16 hi 4608 + fp16 lo 4608)
//   [27648, 101376)   ff ring: 4 slots x 18432 ([h][t] stride 36 floats =
//                     128 x 144 B; consumer reads 8x LDS.128 per head row)
//   W_hi (init only) aliases ff region at 27648 (128 x 144 B = 18432).
// ============================================================================
#define WSTR      72
#define ROWB      144
#define XBUF(s)   ((s) * 9216)
#define SMEM_FF   27648
#define FFB(s)    (SMEM_FF + (s) * 18432)
#define FF_STR    36                   // floats per head row ([h][t] layout)
#define SMEM_W_HI 27648
#define SMEM_TOTAL 101376

// Named barriers (256 threads = 128 producers + 128 consumers):
//   FFREADY(s)=1+s (s 0..3), FFFREE(s)=5+s, XREADY(s)=9+s (s 0..2),
//   XFREE(s)=12+s, 15 = producer-only (128) W_hi hoist guard
#define BAR_SYNC(id)   asm volatile("bar.sync %0, 256;"   :: "r"(id) : "memory")
#define BAR_ARRIVE(id) asm volatile("bar.arrive %0, 256;" :: "r"(id) : "memory")

// ============================================================================
// Helpers
// ============================================================================
__device__ __forceinline__ uint32_t smem_to_u32(const void* p) {
    uint32_t a;
    asm("{ .reg .u64 t; cvta.to.shared.u64 t, %1; cvt.u32.u64 %0, t; }"
        : "=r"(a) : "l"(p));
    return a;
}
__device__ __forceinline__ float tanhf_approx(float x) {
    float y; asm("tanh.approx.f32 %0, %1;" : "=f"(y) : "f"(x)); return y;
}
__device__ __forceinline__ void ldm_x4(uint32_t* r, uint32_t addr) {
    asm volatile("ldmatrix.sync.aligned.m8n8.x4.shared.b16 {%0,%1,%2,%3}, [%4];"
        : "=r"(r[0]), "=r"(r[1]), "=r"(r[2]), "=r"(r[3]) : "r"(addr));
}
__device__ __forceinline__ void mma_f16(float* d, const uint32_t* a, const uint32_t* b) {
    asm volatile(
        "mma.sync.aligned.m16n8k16.row.col.f32.f16.f16.f32 "
        "{%0,%1,%2,%3},{%4,%5,%6,%7},{%8,%9},{%0,%1,%2,%3};"
        : "+f"(d[0]), "+f"(d[1]), "+f"(d[2]), "+f"(d[3])
        : "r"(a[0]), "r"(a[1]), "r"(a[2]), "r"(a[3]), "r"(b[0]), "r"(b[1]));
}
// bitcast __half2 -> uint32
__device__ __forceinline__ uint32_t h2_as_u32(__half2 h) {
    union { __half2 h2; uint32_t u; } cvt;
    cvt.h2 = h;
    return cvt.u;
}
// packed 2-term fp16 split: hi2 = f16x2(v01), lo2 = f16x2(v01 - f32(hi2))
__device__ __forceinline__ void cvt_pack_f16_fast(float4 v, uint2& hi, uint2& lo) {
    __half2 h01 = __floats2half2_rn(v.x, v.y);       // 1x F2FP.PACK
    __half2 h23 = __floats2half2_rn(v.z, v.w);
    float2 f01 = __half22float2(h01);                // back-convert
    float2 f23 = __half22float2(h23);
    __half2 l01 = __floats2half2_rn(v.x - f01.x, v.y - f01.y);
    __half2 l23 = __floats2half2_rn(v.z - f23.x, v.w - f23.y);
    hi.x = h2_as_u32(h01); hi.y = h2_as_u32(h23);
    lo.x = h2_as_u32(l01); lo.y = h2_as_u32(l23);
}
// consumer-side: convert xr regs -> x ring slot s (hi + lo fp16 planes)
__device__ __forceinline__ void convert_to_slot(char* smem, int s, int ct,
                                                const float4* xr) {
#pragma unroll
    for (int q = 0; q < 4; ++q) {
        int idx = ct + (q << 7);
        int row = idx >> 4, c4 = idx & 15;
        uint32_t off = (uint32_t)row * ROWB + c4 * 8;
        uint2 hi, lo; cvt_pack_f16_fast(xr[q], hi, lo);
        *reinterpret_cast<uint2*>(smem + XBUF(s) + off)        = hi;
        *reinterpret_cast<uint2*>(smem + XBUF(s) + 4608 + off) = lo;
    }
}

// ============================================================================
// Warp-specialized kernel (R16 skeleton + [h][t] ff layout / vector LDS-STS).
//   tid 0..127  : consumers — tanh scan (thread = head) + x load/convert
//                 (convert + x-READY published BEFORE the scan)
//   tid 128..255: producers — 2-term fp16 GEMM (A in regs, 64 HMMA/tile)
// ============================================================================
__global__ void __launch_bounds__(256, 2)
snn_encoder_kernel(const float* __restrict__ x, const float* __restrict__ W,
                   const float* __restrict__ bvec, float* __restrict__ out) {
    extern __shared__ char smem[];
    const uint32_t sb = smem_to_u32(smem);
    const int tid = threadIdx.x;
    const int b   = blockIdx.x;
    const float* xb = x + (size_t)b * T_DIM * K_DIM;

    // ---- Cooperative W convert: (2.5*W) fp32 -> fp16 hi only (aliases ff)
    {
        const float4* w4 = reinterpret_cast<const float4*>(W);
#pragma unroll
        for (int q = 0; q < 8; ++q) {
            int idx = tid + (q << 8);            // 2048 float4
            float4 v = __ldg(&w4[idx]);
            v.x *= 2.5f; v.y *= 2.5f; v.z *= 2.5f; v.w *= 2.5f;
            int row = idx >> 4, c4 = idx & 15;
            uint32_t off = (uint32_t)row * ROWB + c4 * 8;
            __half2 h01 = __floats2half2_rn(v.x, v.y);
            __half2 h23 = __floats2half2_rn(v.z, v.w);
            uint2 hi;
            hi.x = h2_as_u32(h01); hi.y = h2_as_u32(h23);
            *reinterpret_cast<uint2*>(smem + SMEM_W_HI + off) = hi;
        }
    }
    __syncthreads();

    if (tid >= 128) {
        // ==================== PRODUCERS ====================
        const int pt   = tid - 128;
        const int lane = pt & 31;
        const int pw   = pt >> 5;                // heads [32pw, 32pw+32)
        const int j    = lane >> 3;

        const uint32_t a_off = (uint32_t)(((j & 1) * 8 + (lane & 7)) * WSTR + ((j >> 1) * 8)) * 2;
        const uint32_t b_off = (uint32_t)(((j >> 1) * 8 + (lane & 7)) * WSTR + ((j & 1) * 8)) * 2;

        // hoist W_hi fragments into registers (ff ring aliases W_hi after)
        uint32_t Ahi[2][4][4];
        {
            const uint32_t aW_hi = sb + SMEM_W_HI + (uint32_t)(pw * 32) * ROWB + a_off;
#pragma unroll
            for (int mt = 0; mt < 2; ++mt)
#pragma unroll
                for (int ks = 0; ks < 4; ++ks)
                    ldm_x4(Ahi[mt][ks], aW_hi + (uint32_t)mt * 16 * ROWB + ks * 32);
        }
        asm volatile("bar.sync 15, 128;" ::: "memory");

        // bias' = 2.5*b - 1.5 folded into accumulator init
        const int r0 = lane >> 2;
        const int c0 = 2 * (lane & 3);
        float bias0[2], bias1[2];
#pragma unroll
        for (int mt = 0; mt < 2; ++mt) {
            bias0[mt] = fmaf(__ldg(&bvec[pw * 32 + mt * 16 + r0]), 2.5f, -1.5f);
            bias1[mt] = fmaf(__ldg(&bvec[pw * 32 + mt * 16 + r0 + 8]), 2.5f, -1.5f);
        }

        int sx = 0, sf = 0;
        for (int i = 0; i < N_TILES; ++i) {
            BAR_SYNC(9 + sx);                    // wait x tile i converted

            float d[2][4][4];
#pragma unroll
            for (int mt = 0; mt < 2; ++mt)
#pragma unroll
                for (int nt = 0; nt < 4; ++nt) {
                    d[mt][nt][0] = bias0[mt]; d[mt][nt][1] = bias0[mt];
                    d[mt][nt][2] = bias1[mt]; d[mt][nt][3] = bias1[mt];
                }
            const uint32_t bX_hi = sb + XBUF(sx) + b_off;
            const uint32_t bX_lo = bX_hi + 4608;
#pragma unroll
            for (int ks = 0; ks < 4; ++ks) {
                uint32_t bh[2][4], bl[2][4];
                ldm_x4(bh[0], bX_hi + ks * 32);
                ldm_x4(bh[1], bX_hi + 16 * ROWB + ks * 32);
                ldm_x4(bl[0], bX_lo + ks * 32);
                ldm_x4(bl[1], bX_lo + 16 * ROWB + ks * 32);
#pragma unroll
                for (int mt = 0; mt < 2; ++mt)
#pragma unroll
                    for (int nt = 0; nt < 4; ++nt) {
                        const uint32_t* bhp = &bh[nt >> 1][(nt & 1) * 2];
                        const uint32_t* blp = &bl[nt >> 1][(nt & 1) * 2];
                        mma_f16(d[mt][nt], Ahi[mt][ks], bhp);   // wh * xh
                        mma_f16(d[mt][nt], Ahi[mt][ks], blp);   // wh * xl
                    }
            }
            BAR_ARRIVE(12 + sx);                 // x slot free (LDSM done)

            if (i >= 4) BAR_SYNC(5 + sf);        // wait ff slot free (ring 4)

            // store ff tile, layout [h][t] stride 36, STS.64 pairs
            {
                float* ffp = reinterpret_cast<float*>(smem + FFB(sf));
                const int baser = pw * 32 + r0;
#pragma unroll
                for (int mt = 0; mt < 2; ++mt) {
                    const int row = baser + mt * 16;
#pragma unroll
                    for (int nt = 0; nt < 4; ++nt) {
                        const int col = nt * 8 + c0;
                        *reinterpret_cast<float2*>(ffp + row * FF_STR + col) =
                            make_float2(d[mt][nt][0], d[mt][nt][1]);
                        *reinterpret_cast<float2*>(ffp + (row + 8) * FF_STR + col) =
                            make_float2(d[mt][nt][2], d[mt][nt][3]);
                    }
                }
            }
            BAR_ARRIVE(1 + sf);                  // ff tile ready

            if (++sx == 3) sx = 0;
            if (++sf == 4) sf = 0;
        }
    } else {
        // ==================== CONSUMERS (scan + x feed) ====================
        const int h  = tid;
        const int ct = tid;
        float* outp = out + (size_t)b * T_DIM * H_DIM + h;

        // prologue: convert x tiles 0,1 into slots 0,1; prefetch tile 2
        float4 xr[4];
        {
            const float4* x4 = reinterpret_cast<const float4*>(xb);
#pragma unroll
            for (int q = 0; q < 4; ++q) xr[q] = __ldg(&x4[ct + (q << 7)]);
            convert_to_slot(smem, 0, ct, xr);
            BAR_ARRIVE(9 + 0);
            x4 = reinterpret_cast<const float4*>(xb + (size_t)TILE_T * K_DIM);
#pragma unroll
            for (int q = 0; q < 4; ++q) xr[q] = __ldg(&x4[ct + (q << 7)]);
            convert_to_slot(smem, 1, ct, xr);
            BAR_ARRIVE(9 + 1);
            x4 = reinterpret_cast<const float4*>(xb + (size_t)2 * TILE_T * K_DIM);
#pragma unroll
            for (int q = 0; q < 4; ++q) xr[q] = __ldg(&x4[ct + (q << 7)]);
        }

        // scan state: z = 0.9*y_{-1} - 1.25*th_{-1} = -1.0 (mem=0, spk=0)
        float z = -1.0f;
        int sf = 0, sx = 2;                      // next convert slot = tile 2

        for (int i = 0; i < N_TILES; ++i) {
            // convert tile i+2 FIRST (publish before scanning), prefetch i+3
            if (i + 2 < N_TILES) {
                if (i + 2 >= 3) BAR_SYNC(12 + sx);
                convert_to_slot(smem, sx, ct, xr);
                BAR_ARRIVE(9 + sx);
                if (++sx == 3) sx = 0;
            }
            if (i + 3 < N_TILES) {
                const float4* x4 = reinterpret_cast<const float4*>(
                    xb + (size_t)(i + 3) * TILE_T * K_DIM);
#pragma unroll
                for (int q = 0; q < 4; ++q) xr[q] = __ldg(&x4[ct + (q << 7)]);
            }

            BAR_SYNC(1 + sf);                    // wait ff tile i
            const float* fp = reinterpret_cast<const float*>(smem + FFB(sf))
                              + h * FF_STR;
            float4 g4[8];                        // 8x LDS.128, conflict-free
#pragma unroll
            for (int q = 0; q < 8; ++q)
                g4[q] = *reinterpret_cast<const float4*>(fp + q * 4);
            BAR_ARRIVE(5 + sf);                  // free ff slot immediately
            if (++sf == 4) sf = 0;

            const float* gf = reinterpret_cast<const float*>(g4);
            float* po = outp + (size_t)i * TILE_T * H_DIM;
            float y = z + gf[0];
#pragma unroll
            for (int t = 0; t < TILE_T; ++t) {
                float th = tanhf_approx(y);          // MUFU (critical path)
                float gn = (t < TILE_T - 1) ? gf[t + 1] : 0.0f;
                float a  = fmaf(0.9f, y, gn);        // parallel with tanh
                y = fmaf(th, -1.25f, a);             // y_{t+1} (or z at t=31)
                float spk = fmaf(th, 0.5f, 0.5f);    // off critical path
                po[(size_t)t * H_DIM] = spk;
            }
            z = y;                               // carry partial to next tile
        }
    }
}

// ============================================================================
// Launch. Inputs: x [256,2048,64] f32, W [128,64] f32, b [128] f32 -> out f32
// ============================================================================
extern "C" void kernel_launch(void* const* d_in, const int* in_sizes, int n_in,
                              void* d_out, int out_size) {
    const float* x = (const float*)d_in[0];
    const float* W = (const float*)d_in[1];
    const float* b = (const float*)d_in[2];
    float* out = (float*)d_out;

    cudaFuncSetAttribute(snn_encoder_kernel,
                         cudaFuncAttributeMaxDynamicSharedMemorySize, SMEM_TOTAL);
    snn_encoder_kernel<<<B_DIM, 256, SMEM_TOTAL>>>(x, W, b, out);
}